// round 4
// baseline (speedup 1.0000x reference)
#include <cuda_runtime.h>
#include <cstdint>

#define SEQ 256
#define VOC 96
#define DD  (SEQ * VOC)     // 24576 dendrites
#define TPITCH 128          // padded row bytes (96 payload)

// int8 quantized log-weight table, [dendrite][class], plus one zero row for
// masked positions. 24577*128 = 3.1 MB (L2-resident).
__device__ __align__(16) signed char g_tab[(DD + 1) * TPITCH];

#define QSCALE   (0.625f / 127.0f)
#define QINV     (127.0f / 0.625f)

// PRMT with sign-replicate mode (bit 3 of nibble). NOTE: __byte_perm masks
// selector nibbles to 3 bits, so the sign-extend mode MUST go via inline asm.
template <unsigned SEL>
__device__ __forceinline__ unsigned prmt_sx(unsigned a) {
    unsigned r;
    asm("prmt.b32 %0, %1, 0, %2;" : "=r"(r) : "r"(a), "n"(SEL));
    return r;
}

// ---------------------------------------------------------------------------
// Kernel 1: q = round(log(2*sigmoid(raw)) / QSCALE) as int8, transposed
// (V,D) -> (D,V) via smem tile. log(2*sigmoid(x)) = ln2 - log1p(exp(-x)).
// ---------------------------------------------------------------------------
__global__ void transform_kernel(const float* __restrict__ raw) {
    __shared__ __align__(16) signed char tile[64][112];  // pitch 112 = 7*16
    const int d0 = blockIdx.x * 64;
    const int t  = threadIdx.x;             // 0..191

    #pragma unroll
    for (int i = t; i < 64 * VOC; i += 192) {
        int v  = i >> 6;
        int dc = i & 63;
        float x = raw[v * DD + d0 + dc];
        float e = __expf(-x);
        float l = __logf(1.0f + e);
        float r = 0.69314718f - l;          // in [-0.6202, 0.3799]
        int q = __float2int_rn(r * QINV);
        q = max(-127, min(127, q));
        tile[dc][v] = (signed char)q;
    }
    __syncthreads();

    // Coalesced uint4 writes: 64 rows x 6 uint4
    #pragma unroll
    for (int i = t; i < 64 * 6; i += 192) {
        int dr = i / 6;
        int j  = i % 6;
        uint4 v = *reinterpret_cast<const uint4*>(&tile[dr][j * 16]);
        *reinterpret_cast<uint4*>(&g_tab[(size_t)(d0 + dr) * TPITCH + j * 16]) = v;
    }

    // Block 0 zeroes the masked-position row (payload 96B)
    if (blockIdx.x == 0 && t < 6) {
        *reinterpret_cast<uint4*>(&g_tab[(size_t)DD * TPITCH + t * 16]) =
            make_uint4(0, 0, 0, 0);
    }
}

// ---------------------------------------------------------------------------
// Kernel 2: gather-sum. Block = 192 threads = 4 samples x 8 seq-eighths x
// 6 uint4-lanes (16 classes each). Branchless: masked positions hit the zero
// row. Accumulate exact s16x2 integer sums (PRMT sign-extend + VADD2).
// ---------------------------------------------------------------------------
__global__ void gather_kernel(const int* __restrict__ chars,
                              float* __restrict__ out, int B) {
    __shared__ int      soff[4 * SEQ];       // [sample][k(32)][eighth(8)] byte offsets
    __shared__ unsigned sfired[4 * 8];       // ballot words: 8 per sample
    __shared__ unsigned sred[192][9];        // partial s16x2 accs (pad 9)

    const int t     = threadIdx.x;           // 0..191
    const int bbase = blockIdx.x * 4;

    // ---- staging: offsets + fired ballots ----
    #pragma unroll
    for (int kk = 0; kk < 6; kk++) {
        int i = kk * 192 + t;
        int c = 0;
        if (i < 4 * SEQ) {
            int b = bbase + (i >> 8);
            int s = i & (SEQ - 1);
            if (b < B) c = chars[b * SEQ + s];
            int dend = (c > 0) ? (s * VOC + c - 1) : DD;
            // interleaved layout: [sample][k][eighth] so the inner-loop LDS
            // for a warp's 6 groups hits consecutive words (no bank conflict)
            soff[(i & ~255) + (s & 31) * 8 + (s >> 5)] = dend * TPITCH;
        }
        unsigned ball = __ballot_sync(0xffffffffu, c > 0);
        if ((t & 31) == 0 && i < 4 * SEQ) sfired[i >> 5] = ball;
    }
    __syncthreads();

    const int sample = t / 48;
    const int sub    = t % 48;
    const int eighth = sub / 6;
    const int lane   = sub % 6;

    const char* tb = reinterpret_cast<const char*>(g_tab) + lane * 16;
    const int*  so = &soff[sample * SEQ + eighth];

    unsigned acc[8];
    #pragma unroll
    for (int r = 0; r < 8; r++) acc[r] = 0;

    #pragma unroll 8
    for (int k = 0; k < 32; k++) {
        int off = so[k * 8];
        uint4 v = *reinterpret_cast<const uint4*>(tb + off);
        // sign-extend int8 pairs to s16x2 and accumulate (exact)
        acc[0] = __vadd2(acc[0], prmt_sx<0x9180>(v.x));
        acc[1] = __vadd2(acc[1], prmt_sx<0xB3A2>(v.x));
        acc[2] = __vadd2(acc[2], prmt_sx<0x9180>(v.y));
        acc[3] = __vadd2(acc[3], prmt_sx<0xB3A2>(v.y));
        acc[4] = __vadd2(acc[4], prmt_sx<0x9180>(v.z));
        acc[5] = __vadd2(acc[5], prmt_sx<0xB3A2>(v.z));
        acc[6] = __vadd2(acc[6], prmt_sx<0x9180>(v.w));
        acc[7] = __vadd2(acc[7], prmt_sx<0xB3A2>(v.w));
    }

    #pragma unroll
    for (int r = 0; r < 8; r++) sred[t][r] = acc[r];
    __syncthreads();

    if (eighth == 0) {
        #pragma unroll
        for (int e = 1; e < 8; e++)
            #pragma unroll
            for (int r = 0; r < 8; r++)
                acc[r] = __vadd2(acc[r], sred[t + e * 6][r]);

        int b = bbase + sample;
        if (b < B) {
            int n = 0;
            #pragma unroll
            for (int w = 0; w < 8; w++) n += __popc(sfired[sample * 8 + w]);
            float zm = QSCALE / fmaxf((float)n, 1.0f);

            float o[16];
            #pragma unroll
            for (int r = 0; r < 8; r++) {
                int lo = (int)(short)(acc[r] & 0xFFFF);
                int hi = ((int)acc[r]) >> 16;
                int j = r >> 1, p = (r & 1) * 2;
                o[j * 4 + p]     = __expf((float)lo * zm);
                o[j * 4 + p + 1] = __expf((float)hi * zm);
            }
            float4* po = reinterpret_cast<float4*>(out + b * VOC + lane * 16);
            po[0] = make_float4(o[0],  o[1],  o[2],  o[3]);
            po[1] = make_float4(o[4],  o[5],  o[6],  o[7]);
            po[2] = make_float4(o[8],  o[9],  o[10], o[11]);
            po[3] = make_float4(o[12], o[13], o[14], o[15]);
        }
    }
}

// ---------------------------------------------------------------------------
extern "C" void kernel_launch(void* const* d_in, const int* in_sizes, int n_in,
                              void* d_out, int out_size) {
    const int*   chars;
    const float* raw;
    int csz;
    if (in_sizes[0] == VOC * DD) {
        raw   = (const float*)d_in[0];
        chars = (const int*)d_in[1];
        csz   = in_sizes[1];
    } else {
        chars = (const int*)d_in[0];
        raw   = (const float*)d_in[1];
        csz   = in_sizes[0];
    }
    const int B = csz / SEQ;

    transform_kernel<<<DD / 64, 192>>>(raw);
    gather_kernel<<<(B + 3) / 4, 192>>>(chars, (float*)d_out, B);
}

// round 6
// speedup vs baseline: 1.5551x; 1.5551x over previous
#include <cuda_runtime.h>
#include <cstdint>

#define SEQ 256
#define VOC 96
#define DD  (SEQ * VOC)     // 24576 dendrites
#define TPITCH 128          // padded row bytes (96 payload)

// int8 quantized log-weight table, [dendrite][class], plus one zero row for
// masked positions. 24577*128 = 3.1 MB (L2-resident).
__device__ __align__(16) signed char g_tab[(DD + 1) * TPITCH];

#define QSCALE   (0.625f / 127.0f)
#define QINV     (127.0f / 0.625f)

// PRMT with sign-replicate mode (bit 3 of nibble). __byte_perm masks selector
// nibbles to 3 bits, so sign-extend mode MUST go via inline asm.
template <unsigned SEL>
__device__ __forceinline__ unsigned prmt_sx(unsigned a) {
    unsigned r;
    asm("prmt.b32 %0, %1, 0, %2;" : "=r"(r) : "r"(a), "n"(SEL));
    return r;
}

// ---------------------------------------------------------------------------
// Kernel 1: q = round(log(2*sigmoid(raw)) / QSCALE) as int8, transposed
// (V,D) -> (D,V) via smem tile. 32 d-cols x 96 v per block, 256 threads,
// grid 768 (~41 warps/SM).
// ---------------------------------------------------------------------------
__global__ __launch_bounds__(256) void transform_kernel(const float* __restrict__ raw) {
    __shared__ __align__(16) signed char tile[32][112];  // pitch 112 = 7*16
    const int d0 = blockIdx.x * 32;
    const int t  = threadIdx.x;             // 0..255

    #pragma unroll
    for (int i = t; i < 32 * VOC; i += 256) {
        int v  = i >> 5;
        int dc = i & 31;
        float x = raw[v * DD + d0 + dc];
        float e = __expf(-x);
        float l = __logf(1.0f + e);
        float r = 0.69314718f - l;          // in [-0.6202, 0.3799]
        int q = __float2int_rn(r * QINV);
        q = max(-127, min(127, q));
        tile[dc][v] = (signed char)q;
    }
    __syncthreads();

    // Coalesced uint4 writes: 32 rows x 6 uint4 = 192
    if (t < 32 * 6) {
        int dr = t / 6;
        int j  = t % 6;
        uint4 v = *reinterpret_cast<const uint4*>(&tile[dr][j * 16]);
        *reinterpret_cast<uint4*>(&g_tab[(size_t)(d0 + dr) * TPITCH + j * 16]) = v;
    }

    // Block 0 zeroes the masked-position row (payload 96B)
    if (blockIdx.x == 0 && t >= 224 && t < 230) {
        *reinterpret_cast<uint4*>(&g_tab[(size_t)DD * TPITCH + (t - 224) * 16]) =
            make_uint4(0, 0, 0, 0);
    }
}

// ---------------------------------------------------------------------------
// Kernel 2: gather-sum. Block = 384 threads = 4 samples x 16 sixteenths x
// 6 uint4-lanes (16 classes each). Branchless: masked positions hit the zero
// row. Exact s16x2 integer accumulation (PRMT sign-extend + VADD2).
// Inner loop batches 8 independent LDG.128 (explicit MLP=8).
// ---------------------------------------------------------------------------
__global__ __launch_bounds__(384, 3) void gather_kernel(const int* __restrict__ chars,
                                                        float* __restrict__ out, int B) {
    __shared__ int      soff[4 * SEQ];       // [sample][k(16)][sixteenth(16)]
    __shared__ unsigned sfired[4 * 8];       // ballot words: 8 per sample
    __shared__ uint4    sredA[384];          // partial s16x2 accs (low 4)
    __shared__ uint4    sredB[384];          // partial s16x2 accs (high 4)

    const int t     = threadIdx.x;           // 0..383
    const int bbase = blockIdx.x * 4;

    // ---- staging: offsets + fired ballots ----
    #pragma unroll
    for (int kk = 0; kk < 3; kk++) {
        int i = kk * 384 + t;
        int c = 0;
        if (i < 4 * SEQ) {
            int b = bbase + (i >> 8);
            int s = i & (SEQ - 1);
            if (b < B) c = chars[b * SEQ + s];
            int dend = (c > 0) ? (s * VOC + c - 1) : DD;
            // interleaved layout: [sample][s&15][s>>4] so thread `sixteenth`
            // reads consecutive smem words across its loop (no conflicts)
            soff[(i & ~255) + (s & 15) * 16 + (s >> 4)] = dend * TPITCH;
        }
        unsigned ball = __ballot_sync(0xffffffffu, c > 0);
        if ((t & 31) == 0 && i < 4 * SEQ) sfired[i >> 5] = ball;
    }
    __syncthreads();

    const int sample    = t / 96;
    const int sub       = t % 96;
    const int sixteenth = sub / 6;
    const int lane      = sub % 6;

    const char* tb = reinterpret_cast<const char*>(g_tab) + lane * 16;
    const int*  so = &soff[sample * SEQ + sixteenth];

    unsigned acc[8];
    #pragma unroll
    for (int r = 0; r < 8; r++) acc[r] = 0;

    #pragma unroll
    for (int kb = 0; kb < 16; kb += 8) {
        uint4 v[8];
        #pragma unroll
        for (int u = 0; u < 8; u++)
            v[u] = *reinterpret_cast<const uint4*>(tb + so[(kb + u) * 16]);
        #pragma unroll
        for (int u = 0; u < 8; u++) {
            acc[0] = __vadd2(acc[0], prmt_sx<0x9180>(v[u].x));
            acc[1] = __vadd2(acc[1], prmt_sx<0xB3A2>(v[u].x));
            acc[2] = __vadd2(acc[2], prmt_sx<0x9180>(v[u].y));
            acc[3] = __vadd2(acc[3], prmt_sx<0xB3A2>(v[u].y));
            acc[4] = __vadd2(acc[4], prmt_sx<0x9180>(v[u].z));
            acc[5] = __vadd2(acc[5], prmt_sx<0xB3A2>(v[u].z));
            acc[6] = __vadd2(acc[6], prmt_sx<0x9180>(v[u].w));
            acc[7] = __vadd2(acc[7], prmt_sx<0xB3A2>(v[u].w));
        }
    }

    sredA[t] = make_uint4(acc[0], acc[1], acc[2], acc[3]);
    sredB[t] = make_uint4(acc[4], acc[5], acc[6], acc[7]);
    __syncthreads();

    if (sixteenth == 0) {
        #pragma unroll
        for (int e = 1; e < 16; e++) {
            uint4 a = sredA[t + e * 6];
            uint4 b = sredB[t + e * 6];
            acc[0] = __vadd2(acc[0], a.x); acc[1] = __vadd2(acc[1], a.y);
            acc[2] = __vadd2(acc[2], a.z); acc[3] = __vadd2(acc[3], a.w);
            acc[4] = __vadd2(acc[4], b.x); acc[5] = __vadd2(acc[5], b.y);
            acc[6] = __vadd2(acc[6], b.z); acc[7] = __vadd2(acc[7], b.w);
        }

        int b = bbase + sample;
        if (b < B) {
            int n = 0;
            #pragma unroll
            for (int w = 0; w < 8; w++) n += __popc(sfired[sample * 8 + w]);
            float zm = QSCALE / fmaxf((float)n, 1.0f);

            float o[16];
            #pragma unroll
            for (int r = 0; r < 8; r++) {
                int lo = (int)(short)(acc[r] & 0xFFFF);
                int hi = ((int)acc[r]) >> 16;
                int j = r >> 1, p = (r & 1) * 2;
                o[j * 4 + p]     = __expf((float)lo * zm);
                o[j * 4 + p + 1] = __expf((float)hi * zm);
            }
            float4* po = reinterpret_cast<float4*>(out + b * VOC + lane * 16);
            po[0] = make_float4(o[0],  o[1],  o[2],  o[3]);
            po[1] = make_float4(o[4],  o[5],  o[6],  o[7]);
            po[2] = make_float4(o[8],  o[9],  o[10], o[11]);
            po[3] = make_float4(o[12], o[13], o[14], o[15]);
        }
    }
}

// ---------------------------------------------------------------------------
extern "C" void kernel_launch(void* const* d_in, const int* in_sizes, int n_in,
                              void* d_out, int out_size) {
    const int*   chars;
    const float* raw;
    int csz;
    if (in_sizes[0] == VOC * DD) {
        raw   = (const float*)d_in[0];
        chars = (const int*)d_in[1];
        csz   = in_sizes[1];
    } else {
        chars = (const int*)d_in[0];
        raw   = (const float*)d_in[1];
        csz   = in_sizes[0];
    }
    const int B = csz / SEQ;

    transform_kernel<<<DD / 32, 256>>>(raw);
    gather_kernel<<<(B + 3) / 4, 384>>>(chars, (float*)d_out, B);
}